// round 5
// baseline (speedup 1.0000x reference)
#include <cuda_runtime.h>
#include <cuda_bf16.h>
#include <cstdint>

// SparseWindowedAttention: B=1, S=4096, E=768, H=12, hd=64, window=128
// R5: GEMM mainloop rebuilt: SW128-swizzled combined hi/lo tiles (no padding),
//     3-stage cp.async pipeline, ONE __syncthreads per K-chunk.
//     Attention unchanged from R4.

#define S_LEN 4096
#define EDIM  768
#define NH    12
#define HD    64
#define QKVN  2304
#define WIN   128

// ------------------------- scratch -------------------------
__device__ __nv_bfloat16 g_xhi[(size_t)S_LEN * EDIM];
__device__ __nv_bfloat16 g_xlo[(size_t)S_LEN * EDIM];
__device__ __nv_bfloat16 g_wqhi[(size_t)QKVN * EDIM];
__device__ __nv_bfloat16 g_wqlo[(size_t)QKVN * EDIM];
__device__ __nv_bfloat16 g_wohi[(size_t)EDIM * EDIM];
__device__ __nv_bfloat16 g_wolo[(size_t)EDIM * EDIM];
__device__ __nv_bfloat16 g_qkvhi[(size_t)S_LEN * QKVN];
__device__ __nv_bfloat16 g_qkvlo[(size_t)S_LEN * QKVN];
__device__ __nv_bfloat16 g_ahi[(size_t)S_LEN * EDIM];
__device__ __nv_bfloat16 g_alo[(size_t)S_LEN * EDIM];

// ------------------------- helpers -------------------------
__device__ __forceinline__ uint32_t smem_u32(const void* p) {
    uint32_t a;
    asm("{ .reg .u64 t; cvta.to.shared.u64 t, %1; cvt.u32.u64 %0, t; }" : "=r"(a) : "l"(p));
    return a;
}

#define CP_ASYNC16(saddr, gptr) \
    asm volatile("cp.async.cg.shared.global [%0], [%1], 16;" :: "r"(saddr), "l"(gptr))
#define CP_COMMIT() asm volatile("cp.async.commit_group;")
#define CP_WAIT1()  asm volatile("cp.async.wait_group 1;")
#define CP_WAIT0()  asm volatile("cp.async.wait_group 0;")

#define SW128(bo) ((bo) ^ (((bo) >> 3) & 0x70))

__device__ __forceinline__ void ldsm_x4(uint32_t* r, uint32_t addr) {
    asm volatile("ldmatrix.sync.aligned.m8n8.x4.shared.b16 {%0,%1,%2,%3}, [%4];"
                 : "=r"(r[0]), "=r"(r[1]), "=r"(r[2]), "=r"(r[3]) : "r"(addr));
}
__device__ __forceinline__ void ldsm_x2(uint32_t* r, uint32_t addr) {
    asm volatile("ldmatrix.sync.aligned.m8n8.x2.shared.b16 {%0,%1}, [%2];"
                 : "=r"(r[0]), "=r"(r[1]) : "r"(addr));
}
__device__ __forceinline__ void ldsm_x2_trans(uint32_t* r, uint32_t addr) {
    asm volatile("ldmatrix.sync.aligned.m8n8.x2.trans.shared.b16 {%0,%1}, [%2];"
                 : "=r"(r[0]), "=r"(r[1]) : "r"(addr));
}
__device__ __forceinline__ void mma_bf16(float* d, const uint32_t* a, const uint32_t* b) {
    asm volatile(
        "mma.sync.aligned.m16n8k16.row.col.f32.bf16.bf16.f32 "
        "{%0,%1,%2,%3}, {%4,%5,%6,%7}, {%8,%9}, {%0,%1,%2,%3};"
        : "+f"(d[0]), "+f"(d[1]), "+f"(d[2]), "+f"(d[3])
        : "r"(a[0]), "r"(a[1]), "r"(a[2]), "r"(a[3]), "r"(b[0]), "r"(b[1]));
}

__device__ __forceinline__ void split2(float x, float y, uint32_t& hi, uint32_t& lo) {
    __nv_bfloat16 hx = __float2bfloat16(x);
    __nv_bfloat16 hy = __float2bfloat16(y);
    __nv_bfloat16 lx = __float2bfloat16(x - __bfloat162float(hx));
    __nv_bfloat16 ly = __float2bfloat16(y - __bfloat162float(hy));
    hi = ((uint32_t)__bfloat16_as_ushort(hy) << 16) | (uint32_t)__bfloat16_as_ushort(hx);
    lo = ((uint32_t)__bfloat16_as_ushort(ly) << 16) | (uint32_t)__bfloat16_as_ushort(lx);
}

// ---------------------------------------------------------------------------
__global__ void split_bf16_kernel(const float4* __restrict__ in,
                                  __nv_bfloat162* __restrict__ hi,
                                  __nv_bfloat162* __restrict__ lo, int n4)
{
    int i = blockIdx.x * blockDim.x + threadIdx.x;
    if (i >= n4) return;
    float4 v = in[i];
    uint32_t h0, l0, h1, l1;
    split2(v.x, v.y, h0, l0);
    split2(v.z, v.w, h1, l1);
    ((uint32_t*)hi)[2*i]   = h0;
    ((uint32_t*)hi)[2*i+1] = h1;
    ((uint32_t*)lo)[2*i]   = l0;
    ((uint32_t*)lo)[2*i+1] = l1;
}

// ---------------------------------------------------------------------------
// GEMM: C = (Ahi+Alo)[M,K] @ (Bhi+Blo)[N,K]^T + bias, mma.sync bf16 3-pass.
// 128x128 CTA tile, BK=32. Stage layout: A tile then B tile, each 128 rows x
// 128B (row = 64B hi | 64B lo), SW128 swizzled. 3 stages, 1 sync per chunk.
// ---------------------------------------------------------------------------
#define TILE_BYTES 16384           // 128 rows * 128 B
#define STAGE_BYTES (2 * TILE_BYTES)
#define NSTAGE 3
#define GEMM_SMEM (NSTAGE * STAGE_BYTES + 1024)

__global__ __launch_bounds__(256) void gemm_tc_kernel(
    const __nv_bfloat16* __restrict__ Ahi, const __nv_bfloat16* __restrict__ Alo,
    const __nv_bfloat16* __restrict__ Bhi, const __nv_bfloat16* __restrict__ Blo,
    const float* __restrict__ bias, float* __restrict__ C,
    __nv_bfloat16* __restrict__ Chi, __nv_bfloat16* __restrict__ Clo,
    int M, int N, int K)
{
    extern __shared__ char smem[];
    const uint32_t sraw = smem_u32(smem);
    const uint32_t sbase = (sraw + 1023u) & ~1023u;

    const int tid  = threadIdx.x;
    const int wid  = tid >> 5;
    const int lane = tid & 31;
    const int bm = blockIdx.y * 128;
    const int bn = blockIdx.x * 128;
    const int nch = K >> 5;

    const int warp_m = wid & 1;
    const int warp_n = wid >> 1;

    // loader mapping: 2 threads per row; each thread: 2 hi + 2 lo chunks per matrix
    const int lrow = tid >> 1;          // 0..127
    const int lsel = tid & 1;           // 0/1

    float acc[4][4][4];
    #pragma unroll
    for (int i = 0; i < 4; i++)
        #pragma unroll
        for (int j = 0; j < 4; j++)
            #pragma unroll
            for (int e = 0; e < 4; e++) acc[i][j][e] = 0.f;

    auto load_stage = [&](int t, int buf) {
        const uint32_t sA = sbase + buf * STAGE_BYTES;
        const uint32_t sB = sA + TILE_BYTES;
        const int k0 = t * 32;
        const __nv_bfloat16* pah = Ahi + (size_t)(bm + lrow) * K + k0;
        const __nv_bfloat16* pal = Alo + (size_t)(bm + lrow) * K + k0;
        const __nv_bfloat16* pbh = Bhi + (size_t)(bn + lrow) * K + k0;
        const __nv_bfloat16* pbl = Blo + (size_t)(bn + lrow) * K + k0;
        #pragma unroll
        for (int j = 0; j < 2; j++) {
            const int c = 2 * lsel + j;                    // 0..3
            const uint32_t ohi = SW128((uint32_t)(lrow * 128 + c * 16));
            const uint32_t olo = SW128((uint32_t)(lrow * 128 + 64 + c * 16));
            CP_ASYNC16(sA + ohi, pah + c * 8);
            CP_ASYNC16(sA + olo, pal + c * 8);
            CP_ASYNC16(sB + ohi, pbh + c * 8);
            CP_ASYNC16(sB + olo, pbl + c * 8);
        }
    };

    load_stage(0, 0); CP_COMMIT();
    load_stage(1, 1); CP_COMMIT();

    const int la_row = lane & 15;
    const int la_kh  = lane >> 4;
    const int lb_row = lane & 7;
    const int lb_kh  = (lane >> 3) & 1;

    for (int t = 0; t < nch; t++) {
        CP_WAIT1();
        __syncthreads();
        if (t + 2 < nch) load_stage(t + 2, (t + 2) % NSTAGE);
        CP_COMMIT();

        const uint32_t sA = sbase + (t % NSTAGE) * STAGE_BYTES;
        const uint32_t sB = sA + TILE_BYTES;

        #pragma unroll
        for (int ks = 0; ks < 2; ks++) {
            uint32_t bhi[4][2], blo[4][2];
            #pragma unroll
            for (int ni = 0; ni < 4; ni++) {
                const uint32_t ro = (uint32_t)((warp_n * 32 + ni * 8 + lb_row) * 128 + ks * 32 + lb_kh * 16);
                ldsm_x2(bhi[ni], sB + SW128(ro));
                ldsm_x2(blo[ni], sB + SW128(ro + 64));
            }
            #pragma unroll
            for (int mi = 0; mi < 4; mi++) {
                uint32_t ahi[4], alo[4];
                const uint32_t ro = (uint32_t)((warp_m * 64 + mi * 16 + la_row) * 128 + ks * 32 + la_kh * 16);
                ldsm_x4(ahi, sA + SW128(ro));
                ldsm_x4(alo, sA + SW128(ro + 64));
                #pragma unroll
                for (int ni = 0; ni < 4; ni++) {
                    mma_bf16(acc[mi][ni], ahi, bhi[ni]);
                    mma_bf16(acc[mi][ni], alo, bhi[ni]);
                    mma_bf16(acc[mi][ni], ahi, blo[ni]);
                }
            }
        }
    }

    #pragma unroll
    for (int mi = 0; mi < 4; mi++) {
        const int row = bm + warp_m * 64 + mi * 16 + (lane >> 2);
        #pragma unroll
        for (int ni = 0; ni < 4; ni++) {
            const int col = bn + warp_n * 32 + ni * 8 + (lane & 3) * 2;
            const float2 bv = *(const float2*)(bias + col);
            float v0 = acc[mi][ni][0] + bv.x, v1 = acc[mi][ni][1] + bv.y;
            float v2 = acc[mi][ni][2] + bv.x, v3 = acc[mi][ni][3] + bv.y;
            if (Chi) {
                uint32_t h0, l0, h1, l1;
                split2(v0, v1, h0, l0);
                split2(v2, v3, h1, l1);
                *(uint32_t*)(Chi + (size_t)row * N + col)       = h0;
                *(uint32_t*)(Clo + (size_t)row * N + col)       = l0;
                *(uint32_t*)(Chi + (size_t)(row + 8) * N + col) = h1;
                *(uint32_t*)(Clo + (size_t)(row + 8) * N + col) = l1;
            } else {
                *(float2*)(C + (size_t)row * N + col)       = make_float2(v0, v1);
                *(float2*)(C + (size_t)(row + 8) * N + col) = make_float2(v2, v3);
            }
        }
    }
}

// ---------------------------------------------------------------------------
// Flash attention on tensor cores (unchanged from R4).
// ---------------------------------------------------------------------------
#define QPITCH 72
#define SQHI 0
#define SQLO 9216
#define SKHI 18432
#define SKLO 27648
#define SVHI 36864
#define SVLO 46080
#define ATTN_SMEM 55296

__global__ __launch_bounds__(128) void attn_tc_kernel(
    const __nv_bfloat16* __restrict__ qkvhi, const __nv_bfloat16* __restrict__ qkvlo,
    __nv_bfloat16* __restrict__ ahi, __nv_bfloat16* __restrict__ alo)
{
    extern __shared__ char smem[];
    const uint32_t sb = smem_u32(smem);

    const int tid  = threadIdx.x;
    const int lane = tid & 31;
    const int wq   = tid >> 5;
    const int h    = blockIdx.y;
    const int q0   = blockIdx.x * 64;

    const int lrow = tid >> 1;
    const int half = tid & 1;
    const uint32_t soff = (uint32_t)(lrow * QPITCH + half * 32) * 2;

    {
        const __nv_bfloat16* sh = qkvhi + (size_t)(q0 + lrow) * QKVN + h * 192 + half * 32;
        const __nv_bfloat16* sl = qkvlo + (size_t)(q0 + lrow) * QKVN + h * 192 + half * 32;
        #pragma unroll
        for (int i = 0; i < 4; i++) {
            *(uint4*)(smem + SQHI + soff + i * 16) = *(const uint4*)(sh + i * 8);
            *(uint4*)(smem + SQLO + soff + i * 16) = *(const uint4*)(sl + i * 8);
        }
    }

    float oacc[8][4];
    #pragma unroll
    for (int ni = 0; ni < 8; ni++)
        #pragma unroll
        for (int e = 0; e < 4; e++) oacc[ni][e] = 0.f;
    float m_a = -1e30f, m_b = -1e30f, l_a = 0.f, l_b = 0.f;

    const int ra = q0 + wq * 16 + (lane >> 2);
    const int rb = ra + 8;

    for (int kb = 0; kb < 5; kb++) {
        const int jbase = q0 - WIN + kb * 64;
        __syncthreads();
        {
            const int g = jbase + lrow;
            const bool v = (g >= 0) && (g < S_LEN);
            const size_t gb = (size_t)(v ? g : 0) * QKVN + h * 192 + half * 32;
            const uint4 z = make_uint4(0, 0, 0, 0);
            #pragma unroll
            for (int i = 0; i < 4; i++) {
                *(uint4*)(smem + SKHI + soff + i*16) = v ? *(const uint4*)(qkvhi + gb + 64  + i*8) : z;
                *(uint4*)(smem + SKLO + soff + i*16) = v ? *(const uint4*)(qkvlo + gb + 64  + i*8) : z;
                *(uint4*)(smem + SVHI + soff + i*16) = v ? *(const uint4*)(qkvhi + gb + 128 + i*8) : z;
                *(uint4*)(smem + SVLO + soff + i*16) = v ? *(const uint4*)(qkvlo + gb + 128 + i*8) : z;
            }
        }
        __syncthreads();

        float sacc[8][4];
        #pragma unroll
        for (int ni = 0; ni < 8; ni++)
            #pragma unroll
            for (int e = 0; e < 4; e++) sacc[ni][e] = 0.f;

        #pragma unroll
        for (int ks = 0; ks < 4; ks++) {
            uint32_t aqh[4], aql[4];
            const uint32_t qoff = (uint32_t)((wq*16 + (lane & 15)) * QPITCH + ks*16 + (lane >> 4) * 8) * 2;
            ldsm_x4(aqh, sb + SQHI + qoff);
            ldsm_x4(aql, sb + SQLO + qoff);
            #pragma unroll
            for (int ni = 0; ni < 8; ni++) {
                uint32_t bh[2], bl[2];
                const uint32_t koff = (uint32_t)((ni*8 + (lane & 7)) * QPITCH + ks*16 + ((lane >> 3) & 1) * 8) * 2;
                ldsm_x2(bh, sb + SKHI + koff);
                ldsm_x2(bl, sb + SKLO + koff);
                mma_bf16(sacc[ni], aqh, bh);
                mma_bf16(sacc[ni], aql, bh);
                mma_bf16(sacc[ni], aqh, bl);
            }
        }

        float mk_a = -1e30f, mk_b = -1e30f;
        #pragma unroll
        for (int ni = 0; ni < 8; ni++) {
            const int j0 = jbase + ni * 8 + (lane & 3) * 2;
            #pragma unroll
            for (int e = 0; e < 4; e++) {
                const int g = j0 + (e & 1);
                const int r = (e < 2) ? ra : rb;
                const int d = r - g;
                const bool ok = (g >= 0) && (g < S_LEN) && (d <= WIN) && (d >= -WIN);
                const float s = ok ? sacc[ni][e] * 0.125f : -1e30f;
                sacc[ni][e] = s;
                if (e < 2) mk_a = fmaxf(mk_a, s); else mk_b = fmaxf(mk_b, s);
            }
        }
        mk_a = fmaxf(mk_a, __shfl_xor_sync(0xffffffffu, mk_a, 1));
        mk_a = fmaxf(mk_a, __shfl_xor_sync(0xffffffffu, mk_a, 2));
        mk_b = fmaxf(mk_b, __shfl_xor_sync(0xffffffffu, mk_b, 1));
        mk_b = fmaxf(mk_b, __shfl_xor_sync(0xffffffffu, mk_b, 2));

        const float mn_a = fmaxf(m_a, mk_a);
        const float mn_b = fmaxf(m_b, mk_b);
        const float corr_a = __expf(m_a - mn_a);
        const float corr_b = __expf(m_b - mn_b);
        const float sm_a = (mn_a < -1e29f) ? 0.f : mn_a;
        const float sm_b = (mn_b < -1e29f) ? 0.f : mn_b;

        float su_a = 0.f, su_b = 0.f;
        #pragma unroll
        for (int ni = 0; ni < 8; ni++) {
            #pragma unroll
            for (int e = 0; e < 4; e++) {
                const float p = __expf(sacc[ni][e] - ((e < 2) ? sm_a : sm_b));
                sacc[ni][e] = p;
                if (e < 2) su_a += p; else su_b += p;
            }
        }
        su_a += __shfl_xor_sync(0xffffffffu, su_a, 1);
        su_a += __shfl_xor_sync(0xffffffffu, su_a, 2);
        su_b += __shfl_xor_sync(0xffffffffu, su_b, 1);
        su_b += __shfl_xor_sync(0xffffffffu, su_b, 2);

        l_a = l_a * corr_a + su_a;
        l_b = l_b * corr_b + su_b;
        m_a = mn_a; m_b = mn_b;

        #pragma unroll
        for (int ni = 0; ni < 8; ni++) {
            oacc[ni][0] *= corr_a; oacc[ni][1] *= corr_a;
            oacc[ni][2] *= corr_b; oacc[ni][3] *= corr_b;
        }

        #pragma unroll
        for (int kk = 0; kk < 4; kk++) {
            uint32_t aph[4], apl[4];
            split2(sacc[2*kk][0],   sacc[2*kk][1],   aph[0], apl[0]);
            split2(sacc[2*kk][2],   sacc[2*kk][3],   aph[1], apl[1]);
            split2(sacc[2*kk+1][0], sacc[2*kk+1][1], aph[2], apl[2]);
            split2(sacc[2*kk+1][2], sacc[2*kk+1][3], aph[3], apl[3]);
            #pragma unroll
            for (int ni = 0; ni < 8; ni++) {
                uint32_t bvh[2], bvl[2];
                const uint32_t voff = (uint32_t)((kk*16 + (lane & 15)) * QPITCH + ni * 8) * 2;
                ldsm_x2_trans(bvh, sb + SVHI + voff);
                ldsm_x2_trans(bvl, sb + SVLO + voff);
                mma_bf16(oacc[ni], aph, bvh);
                mma_bf16(oacc[ni], apl, bvh);
                mma_bf16(oacc[ni], aph, bvl);
            }
        }
    }

    const float inv_a = (l_a > 0.f) ? 1.f / l_a : 0.f;
    const float inv_b = (l_b > 0.f) ? 1.f / l_b : 0.f;
    #pragma unroll
    for (int ni = 0; ni < 8; ni++) {
        const int d = h * 64 + ni * 8 + (lane & 3) * 2;
        uint32_t h0, l0, h1, l1;
        split2(oacc[ni][0] * inv_a, oacc[ni][1] * inv_a, h0, l0);
        split2(oacc[ni][2] * inv_b, oacc[ni][3] * inv_b, h1, l1);
        *(uint32_t*)(ahi + (size_t)ra * EDIM + d) = h0;
        *(uint32_t*)(alo + (size_t)ra * EDIM + d) = l0;
        *(uint32_t*)(ahi + (size_t)rb * EDIM + d) = h1;
        *(uint32_t*)(alo + (size_t)rb * EDIM + d) = l1;
    }
}

// ---------------------------------------------------------------------------
extern "C" void kernel_launch(void* const* d_in, const int* in_sizes, int n_in,
                              void* d_out, int out_size)
{
    const float* x    = (const float*)d_in[0];
    const float* Wqkv = (const float*)d_in[1];
    const float* bqkv = (const float*)d_in[2];
    const float* Wo   = (const float*)d_in[3];
    const float* bo   = (const float*)d_in[4];
    float* out = (float*)d_out;

    __nv_bfloat16 *xhi, *xlo, *wqhi, *wqlo, *wohi, *wolo, *qkvhi, *qkvlo, *ahi, *alo;
    cudaGetSymbolAddress((void**)&xhi,   g_xhi);
    cudaGetSymbolAddress((void**)&xlo,   g_xlo);
    cudaGetSymbolAddress((void**)&wqhi,  g_wqhi);
    cudaGetSymbolAddress((void**)&wqlo,  g_wqlo);
    cudaGetSymbolAddress((void**)&wohi,  g_wohi);
    cudaGetSymbolAddress((void**)&wolo,  g_wolo);
    cudaGetSymbolAddress((void**)&qkvhi, g_qkvhi);
    cudaGetSymbolAddress((void**)&qkvlo, g_qkvlo);
    cudaGetSymbolAddress((void**)&ahi,   g_ahi);
    cudaGetSymbolAddress((void**)&alo,   g_alo);

    cudaFuncSetAttribute(gemm_tc_kernel, cudaFuncAttributeMaxDynamicSharedMemorySize, GEMM_SMEM);
    cudaFuncSetAttribute(attn_tc_kernel, cudaFuncAttributeMaxDynamicSharedMemorySize, ATTN_SMEM);

    {
        int n4 = (S_LEN * EDIM) / 4;
        split_bf16_kernel<<<(n4 + 255) / 256, 256>>>(
            (const float4*)x, (__nv_bfloat162*)xhi, (__nv_bfloat162*)xlo, n4);
    }
    {
        int n4 = (QKVN * EDIM) / 4;
        split_bf16_kernel<<<(n4 + 255) / 256, 256>>>(
            (const float4*)Wqkv, (__nv_bfloat162*)wqhi, (__nv_bfloat162*)wqlo, n4);
    }
    {
        int n4 = (EDIM * EDIM) / 4;
        split_bf16_kernel<<<(n4 + 255) / 256, 256>>>(
            (const float4*)Wo, (__nv_bfloat162*)wohi, (__nv_bfloat162*)wolo, n4);
    }

    // 1) QKV projection -> bf16 hi/lo
    gemm_tc_kernel<<<dim3(QKVN / 128, S_LEN / 128), 256, GEMM_SMEM>>>(
        xhi, xlo, wqhi, wqlo, bqkv, nullptr, qkvhi, qkvlo, S_LEN, QKVN, EDIM);

    // 2) flash attention on tensor cores -> bf16 hi/lo
    attn_tc_kernel<<<dim3(S_LEN / 64, NH), 128, ATTN_SMEM>>>(qkvhi, qkvlo, ahi, alo);

    // 3) output projection -> fp32 out
    gemm_tc_kernel<<<dim3(EDIM / 128, S_LEN / 128), 256, GEMM_SMEM>>>(
        ahi, alo, wohi, wolo, bo, out, nullptr, nullptr, S_LEN, EDIM, EDIM);
}

// round 6
// speedup vs baseline: 1.0683x; 1.0683x over previous
#include <cuda_runtime.h>
#include <cuda_bf16.h>
#include <cstdint>

// SparseWindowedAttention: B=1, S=4096, E=768, H=12, hd=64, window=128
// R6: R5's single-sync 3-stage GEMM pipeline + __launch_bounds__(256,2) to
//     restore 2 CTAs/SM (R5 regressed because regs hit 168 -> 1 CTA/SM).
//     Row-constant swizzle addressing. Attention unchanged from R4.

#define S_LEN 4096
#define EDIM  768
#define NH    12
#define HD    64
#define QKVN  2304
#define WIN   128

// ------------------------- scratch -------------------------
__device__ __nv_bfloat16 g_xhi[(size_t)S_LEN * EDIM];
__device__ __nv_bfloat16 g_xlo[(size_t)S_LEN * EDIM];
__device__ __nv_bfloat16 g_wqhi[(size_t)QKVN * EDIM];
__device__ __nv_bfloat16 g_wqlo[(size_t)QKVN * EDIM];
__device__ __nv_bfloat16 g_wohi[(size_t)EDIM * EDIM];
__device__ __nv_bfloat16 g_wolo[(size_t)EDIM * EDIM];
__device__ __nv_bfloat16 g_qkvhi[(size_t)S_LEN * QKVN];
__device__ __nv_bfloat16 g_qkvlo[(size_t)S_LEN * QKVN];
__device__ __nv_bfloat16 g_ahi[(size_t)S_LEN * EDIM];
__device__ __nv_bfloat16 g_alo[(size_t)S_LEN * EDIM];

// ------------------------- helpers -------------------------
__device__ __forceinline__ uint32_t smem_u32(const void* p) {
    uint32_t a;
    asm("{ .reg .u64 t; cvta.to.shared.u64 t, %1; cvt.u32.u64 %0, t; }" : "=r"(a) : "l"(p));
    return a;
}

#define CP_ASYNC16(saddr, gptr) \
    asm volatile("cp.async.cg.shared.global [%0], [%1], 16;" :: "r"(saddr), "l"(gptr))
#define CP_COMMIT() asm volatile("cp.async.commit_group;")
#define CP_WAIT1()  asm volatile("cp.async.wait_group 1;")

#define SW128(bo) ((bo) ^ (((bo) >> 3) & 0x70))

__device__ __forceinline__ void ldsm_x4(uint32_t* r, uint32_t addr) {
    asm volatile("ldmatrix.sync.aligned.m8n8.x4.shared.b16 {%0,%1,%2,%3}, [%4];"
                 : "=r"(r[0]), "=r"(r[1]), "=r"(r[2]), "=r"(r[3]) : "r"(addr));
}
__device__ __forceinline__ void ldsm_x2(uint32_t* r, uint32_t addr) {
    asm volatile("ldmatrix.sync.aligned.m8n8.x2.shared.b16 {%0,%1}, [%2];"
                 : "=r"(r[0]), "=r"(r[1]) : "r"(addr));
}
__device__ __forceinline__ void ldsm_x2_trans(uint32_t* r, uint32_t addr) {
    asm volatile("ldmatrix.sync.aligned.m8n8.x2.trans.shared.b16 {%0,%1}, [%2];"
                 : "=r"(r[0]), "=r"(r[1]) : "r"(addr));
}
__device__ __forceinline__ void mma_bf16(float* d, const uint32_t* a, const uint32_t* b) {
    asm volatile(
        "mma.sync.aligned.m16n8k16.row.col.f32.bf16.bf16.f32 "
        "{%0,%1,%2,%3}, {%4,%5,%6,%7}, {%8,%9}, {%0,%1,%2,%3};"
        : "+f"(d[0]), "+f"(d[1]), "+f"(d[2]), "+f"(d[3])
        : "r"(a[0]), "r"(a[1]), "r"(a[2]), "r"(a[3]), "r"(b[0]), "r"(b[1]));
}

__device__ __forceinline__ void split2(float x, float y, uint32_t& hi, uint32_t& lo) {
    __nv_bfloat16 hx = __float2bfloat16(x);
    __nv_bfloat16 hy = __float2bfloat16(y);
    __nv_bfloat16 lx = __float2bfloat16(x - __bfloat162float(hx));
    __nv_bfloat16 ly = __float2bfloat16(y - __bfloat162float(hy));
    hi = ((uint32_t)__bfloat16_as_ushort(hy) << 16) | (uint32_t)__bfloat16_as_ushort(hx);
    lo = ((uint32_t)__bfloat16_as_ushort(ly) << 16) | (uint32_t)__bfloat16_as_ushort(lx);
}

// ---------------------------------------------------------------------------
__global__ void split_bf16_kernel(const float4* __restrict__ in,
                                  __nv_bfloat162* __restrict__ hi,
                                  __nv_bfloat162* __restrict__ lo, int n4)
{
    int i = blockIdx.x * blockDim.x + threadIdx.x;
    if (i >= n4) return;
    float4 v = in[i];
    uint32_t h0, l0, h1, l1;
    split2(v.x, v.y, h0, l0);
    split2(v.z, v.w, h1, l1);
    ((uint32_t*)hi)[2*i]   = h0;
    ((uint32_t*)hi)[2*i+1] = h1;
    ((uint32_t*)lo)[2*i]   = l0;
    ((uint32_t*)lo)[2*i+1] = l1;
}

// ---------------------------------------------------------------------------
// GEMM: C = (Ahi+Alo)[M,K] @ (Bhi+Blo)[N,K]^T + bias, mma.sync bf16 3-pass.
// 128x128 CTA tile, BK=32. Stage = A tile | B tile, 128 rows x 128B
// (row = 64B hi | 64B lo), SW128. 3 stages, ONE sync per chunk.
// __launch_bounds__(256, 2) pins regs <= 128 -> 2 CTAs/SM.
// ---------------------------------------------------------------------------
#define TILE_BYTES 16384
#define STAGE_BYTES (2 * TILE_BYTES)
#define NSTAGE 3
#define GEMM_SMEM (NSTAGE * STAGE_BYTES + 1024)

__global__ __launch_bounds__(256, 2) void gemm_tc_kernel(
    const __nv_bfloat16* __restrict__ Ahi, const __nv_bfloat16* __restrict__ Alo,
    const __nv_bfloat16* __restrict__ Bhi, const __nv_bfloat16* __restrict__ Blo,
    const float* __restrict__ bias, float* __restrict__ C,
    __nv_bfloat16* __restrict__ Chi, __nv_bfloat16* __restrict__ Clo,
    int M, int N, int K)
{
    extern __shared__ char smem[];
    const uint32_t sraw = smem_u32(smem);
    const uint32_t sbase = (sraw + 1023u) & ~1023u;

    const int tid  = threadIdx.x;
    const int wid  = tid >> 5;
    const int lane = tid & 31;
    const int bm = blockIdx.y * 128;
    const int bn = blockIdx.x * 128;
    const int nch = K >> 5;

    const int warp_m = wid & 1;
    const int warp_n = wid >> 1;

    // loader mapping: 2 threads per row, 2 16B chunks each per tile half
    const int lrow = tid >> 1;
    const int lsel = tid & 1;
    // SW128(row*128 + c) = row*128 + (c ^ ((row&7)<<4)) for c < 128
    const uint32_t lsw = (uint32_t)((lrow & 7) << 4);
    const uint32_t lrowbase = (uint32_t)lrow * 128;
    const uint32_t lc0 = ((uint32_t)(2 * lsel) * 16) ^ lsw;        // chunk 0 (hi)
    const uint32_t lc1 = ((uint32_t)(2 * lsel + 1) * 16) ^ lsw;    // chunk 1 (hi)
    const uint32_t lc0l = ((uint32_t)(2 * lsel) * 16 + 64) ^ lsw;  // chunk 0 (lo)
    const uint32_t lc1l = ((uint32_t)(2 * lsel + 1) * 16 + 64) ^ lsw;

    const __nv_bfloat16* gah = Ahi + (size_t)(bm + lrow) * K + 2 * lsel * 8;
    const __nv_bfloat16* gal = Alo + (size_t)(bm + lrow) * K + 2 * lsel * 8;
    const __nv_bfloat16* gbh = Bhi + (size_t)(bn + lrow) * K + 2 * lsel * 8;
    const __nv_bfloat16* gbl = Blo + (size_t)(bn + lrow) * K + 2 * lsel * 8;

    float acc[4][4][4];
    #pragma unroll
    for (int i = 0; i < 4; i++)
        #pragma unroll
        for (int j = 0; j < 4; j++)
            #pragma unroll
            for (int e = 0; e < 4; e++) acc[i][j][e] = 0.f;

    auto load_stage = [&](int t, int buf) {
        const uint32_t sA = sbase + buf * STAGE_BYTES + lrowbase;
        const uint32_t sB = sA + TILE_BYTES;
        const int k0 = t * 32;
        CP_ASYNC16(sA + lc0,  gah + k0);
        CP_ASYNC16(sA + lc1,  gah + k0 + 8);
        CP_ASYNC16(sA + lc0l, gal + k0);
        CP_ASYNC16(sA + lc1l, gal + k0 + 8);
        CP_ASYNC16(sB + lc0,  gbh + k0);
        CP_ASYNC16(sB + lc1,  gbh + k0 + 8);
        CP_ASYNC16(sB + lc0l, gbl + k0);
        CP_ASYNC16(sB + lc1l, gbl + k0 + 8);
    };

    load_stage(0, 0); CP_COMMIT();
    load_stage(1, 1); CP_COMMIT();

    // ldsm row constants
    const int la_row = lane & 15;
    const int la_kh  = lane >> 4;
    const int lb_row = lane & 7;
    const int lb_kh  = (lane >> 3) & 1;

    // A: per-mi row and its swizzle constant
    uint32_t a_rowbase[4], a_sw[4];
    #pragma unroll
    for (int mi = 0; mi < 4; mi++) {
        const int row = warp_m * 64 + mi * 16 + la_row;
        a_rowbase[mi] = (uint32_t)row * 128;
        a_sw[mi] = (uint32_t)((row & 7) << 4);
    }
    uint32_t b_rowbase[4], b_sw[4];
    #pragma unroll
    for (int ni = 0; ni < 4; ni++) {
        const int row = warp_n * 32 + ni * 8 + lb_row;
        b_rowbase[ni] = (uint32_t)row * 128;
        b_sw[ni] = (uint32_t)((row & 7) << 4);
    }

    int buf = 0;
    for (int t = 0; t < nch; t++) {
        CP_WAIT1();
        __syncthreads();
        if (t + 2 < nch) {
            int b2 = buf + 2; if (b2 >= NSTAGE) b2 -= NSTAGE;
            load_stage(t + 2, b2);
        }
        CP_COMMIT();

        const uint32_t sA = sbase + buf * STAGE_BYTES;
        const uint32_t sB = sA + TILE_BYTES;

        #pragma unroll
        for (int ks = 0; ks < 2; ks++) {
            const uint32_t akoff = (uint32_t)(ks * 32 + la_kh * 16);
            const uint32_t bkoff = (uint32_t)(ks * 32 + lb_kh * 16);
            uint32_t bhi[4][2], blo[4][2];
            #pragma unroll
            for (int ni = 0; ni < 4; ni++) {
                const uint32_t base = sB + b_rowbase[ni];
                ldsm_x2(bhi[ni], base + (bkoff ^ b_sw[ni]));
                ldsm_x2(blo[ni], base + ((bkoff + 64) ^ b_sw[ni]));
            }
            #pragma unroll
            for (int mi = 0; mi < 4; mi++) {
                uint32_t ahi[4], alo[4];
                const uint32_t base = sA + a_rowbase[mi];
                ldsm_x4(ahi, base + (akoff ^ a_sw[mi]));
                ldsm_x4(alo, base + ((akoff + 64) ^ a_sw[mi]));
                #pragma unroll
                for (int ni = 0; ni < 4; ni++) {
                    mma_bf16(acc[mi][ni], ahi, bhi[ni]);
                    mma_bf16(acc[mi][ni], alo, bhi[ni]);
                    mma_bf16(acc[mi][ni], ahi, blo[ni]);
                }
            }
        }
        buf++; if (buf >= NSTAGE) buf = 0;
    }

    #pragma unroll
    for (int mi = 0; mi < 4; mi++) {
        const int row = bm + warp_m * 64 + mi * 16 + (lane >> 2);
        #pragma unroll
        for (int ni = 0; ni < 4; ni++) {
            const int col = bn + warp_n * 32 + ni * 8 + (lane & 3) * 2;
            const float2 bv = *(const float2*)(bias + col);
            float v0 = acc[mi][ni][0] + bv.x, v1 = acc[mi][ni][1] + bv.y;
            float v2 = acc[mi][ni][2] + bv.x, v3 = acc[mi][ni][3] + bv.y;
            if (Chi) {
                uint32_t h0, l0, h1, l1;
                split2(v0, v1, h0, l0);
                split2(v2, v3, h1, l1);
                *(uint32_t*)(Chi + (size_t)row * N + col)       = h0;
                *(uint32_t*)(Clo + (size_t)row * N + col)       = l0;
                *(uint32_t*)(Chi + (size_t)(row + 8) * N + col) = h1;
                *(uint32_t*)(Clo + (size_t)(row + 8) * N + col) = l1;
            } else {
                *(float2*)(C + (size_t)row * N + col)       = make_float2(v0, v1);
                *(float2*)(C + (size_t)(row + 8) * N + col) = make_float2(v2, v3);
            }
        }
    }
}

// ---------------------------------------------------------------------------
// Flash attention on tensor cores (unchanged from R4).
// ---------------------------------------------------------------------------
#define QPITCH 72
#define SQHI 0
#define SQLO 9216
#define SKHI 18432
#define SKLO 27648
#define SVHI 36864
#define SVLO 46080
#define ATTN_SMEM 55296

__global__ __launch_bounds__(128) void attn_tc_kernel(
    const __nv_bfloat16* __restrict__ qkvhi, const __nv_bfloat16* __restrict__ qkvlo,
    __nv_bfloat16* __restrict__ ahi, __nv_bfloat16* __restrict__ alo)
{
    extern __shared__ char smem[];
    const uint32_t sb = smem_u32(smem);

    const int tid  = threadIdx.x;
    const int lane = tid & 31;
    const int wq   = tid >> 5;
    const int h    = blockIdx.y;
    const int q0   = blockIdx.x * 64;

    const int lrow = tid >> 1;
    const int half = tid & 1;
    const uint32_t soff = (uint32_t)(lrow * QPITCH + half * 32) * 2;

    {
        const __nv_bfloat16* sh = qkvhi + (size_t)(q0 + lrow) * QKVN + h * 192 + half * 32;
        const __nv_bfloat16* sl = qkvlo + (size_t)(q0 + lrow) * QKVN + h * 192 + half * 32;
        #pragma unroll
        for (int i = 0; i < 4; i++) {
            *(uint4*)(smem + SQHI + soff + i * 16) = *(const uint4*)(sh + i * 8);
            *(uint4*)(smem + SQLO + soff + i * 16) = *(const uint4*)(sl + i * 8);
        }
    }

    float oacc[8][4];
    #pragma unroll
    for (int ni = 0; ni < 8; ni++)
        #pragma unroll
        for (int e = 0; e < 4; e++) oacc[ni][e] = 0.f;
    float m_a = -1e30f, m_b = -1e30f, l_a = 0.f, l_b = 0.f;

    const int ra = q0 + wq * 16 + (lane >> 2);
    const int rb = ra + 8;

    for (int kb = 0; kb < 5; kb++) {
        const int jbase = q0 - WIN + kb * 64;
        __syncthreads();
        {
            const int g = jbase + lrow;
            const bool v = (g >= 0) && (g < S_LEN);
            const size_t gb = (size_t)(v ? g : 0) * QKVN + h * 192 + half * 32;
            const uint4 z = make_uint4(0, 0, 0, 0);
            #pragma unroll
            for (int i = 0; i < 4; i++) {
                *(uint4*)(smem + SKHI + soff + i*16) = v ? *(const uint4*)(qkvhi + gb + 64  + i*8) : z;
                *(uint4*)(smem + SKLO + soff + i*16) = v ? *(const uint4*)(qkvlo + gb + 64  + i*8) : z;
                *(uint4*)(smem + SVHI + soff + i*16) = v ? *(const uint4*)(qkvhi + gb + 128 + i*8) : z;
                *(uint4*)(smem + SVLO + soff + i*16) = v ? *(const uint4*)(qkvlo + gb + 128 + i*8) : z;
            }
        }
        __syncthreads();

        float sacc[8][4];
        #pragma unroll
        for (int ni = 0; ni < 8; ni++)
            #pragma unroll
            for (int e = 0; e < 4; e++) sacc[ni][e] = 0.f;

        #pragma unroll
        for (int ks = 0; ks < 4; ks++) {
            uint32_t aqh[4], aql[4];
            const uint32_t qoff = (uint32_t)((wq*16 + (lane & 15)) * QPITCH + ks*16 + (lane >> 4) * 8) * 2;
            ldsm_x4(aqh, sb + SQHI + qoff);
            ldsm_x4(aql, sb + SQLO + qoff);
            #pragma unroll
            for (int ni = 0; ni < 8; ni++) {
                uint32_t bh[2], bl[2];
                const uint32_t koff = (uint32_t)((ni*8 + (lane & 7)) * QPITCH + ks*16 + ((lane >> 3) & 1) * 8) * 2;
                ldsm_x2(bh, sb + SKHI + koff);
                ldsm_x2(bl, sb + SKLO + koff);
                mma_bf16(sacc[ni], aqh, bh);
                mma_bf16(sacc[ni], aql, bh);
                mma_bf16(sacc[ni], aqh, bl);
            }
        }

        float mk_a = -1e30f, mk_b = -1e30f;
        #pragma unroll
        for (int ni = 0; ni < 8; ni++) {
            const int j0 = jbase + ni * 8 + (lane & 3) * 2;
            #pragma unroll
            for (int e = 0; e < 4; e++) {
                const int g = j0 + (e & 1);
                const int r = (e < 2) ? ra : rb;
                const int d = r - g;
                const bool ok = (g >= 0) && (g < S_LEN) && (d <= WIN) && (d >= -WIN);
                const float s = ok ? sacc[ni][e] * 0.125f : -1e30f;
                sacc[ni][e] = s;
                if (e < 2) mk_a = fmaxf(mk_a, s); else mk_b = fmaxf(mk_b, s);
            }
        }
        mk_a = fmaxf(mk_a, __shfl_xor_sync(0xffffffffu, mk_a, 1));
        mk_a = fmaxf(mk_a, __shfl_xor_sync(0xffffffffu, mk_a, 2));
        mk_b = fmaxf(mk_b, __shfl_xor_sync(0xffffffffu, mk_b, 1));
        mk_b = fmaxf(mk_b, __shfl_xor_sync(0xffffffffu, mk_b, 2));

        const float mn_a = fmaxf(m_a, mk_a);
        const float mn_b = fmaxf(m_b, mk_b);
        const float corr_a = __expf(m_a - mn_a);
        const float corr_b = __expf(m_b - mn_b);
        const float sm_a = (mn_a < -1e29f) ? 0.f : mn_a;
        const float sm_b = (mn_b < -1e29f) ? 0.f : mn_b;

        float su_a = 0.f, su_b = 0.f;
        #pragma unroll
        for (int ni = 0; ni < 8; ni++) {
            #pragma unroll
            for (int e = 0; e < 4; e++) {
                const float p = __expf(sacc[ni][e] - ((e < 2) ? sm_a : sm_b));
                sacc[ni][e] = p;
                if (e < 2) su_a += p; else su_b += p;
            }
        }
        su_a += __shfl_xor_sync(0xffffffffu, su_a, 1);
        su_a += __shfl_xor_sync(0xffffffffu, su_a, 2);
        su_b += __shfl_xor_sync(0xffffffffu, su_b, 1);
        su_b += __shfl_xor_sync(0xffffffffu, su_b, 2);

        l_a = l_a * corr_a + su_a;
        l_b = l_b * corr_b + su_b;
        m_a = mn_a; m_b = mn_b;

        #pragma unroll
        for (int ni = 0; ni < 8; ni++) {
            oacc[ni][0] *= corr_a; oacc[ni][1] *= corr_a;
            oacc[ni][2] *= corr_b; oacc[ni][3] *= corr_b;
        }

        #pragma unroll
        for (int kk = 0; kk < 4; kk++) {
            uint32_t aph[4], apl[4];
            split2(sacc[2*kk][0],   sacc[2*kk][1],   aph[0], apl[0]);
            split2(sacc[2*kk][2],   sacc[2*kk][3],   aph[1], apl[1]);
            split2(sacc[2*kk+1][0], sacc[2*kk+1][1], aph[2], apl[2]);
            split2(sacc[2*kk+1][2], sacc[2*kk+1][3], aph[3], apl[3]);
            #pragma unroll
            for (int ni = 0; ni < 8; ni++) {
                uint32_t bvh[2], bvl[2];
                const uint32_t voff = (uint32_t)((kk*16 + (lane & 15)) * QPITCH + ni * 8) * 2;
                ldsm_x2_trans(bvh, sb + SVHI + voff);
                ldsm_x2_trans(bvl, sb + SVLO + voff);
                mma_bf16(oacc[ni], aph, bvh);
                mma_bf16(oacc[ni], apl, bvh);
                mma_bf16(oacc[ni], aph, bvl);
            }
        }
    }

    const float inv_a = (l_a > 0.f) ? 1.f / l_a : 0.f;
    const float inv_b = (l_b > 0.f) ? 1.f / l_b : 0.f;
    #pragma unroll
    for (int ni = 0; ni < 8; ni++) {
        const int d = h * 64 + ni * 8 + (lane & 3) * 2;
        uint32_t h0, l0, h1, l1;
        split2(oacc[ni][0] * inv_a, oacc[ni][1] * inv_a, h0, l0);
        split2(oacc[ni][2] * inv_b, oacc[ni][3] * inv_b, h1, l1);
        *(uint32_t*)(ahi + (size_t)ra * EDIM + d) = h0;
        *(uint32_t*)(alo + (size_t)ra * EDIM + d) = l0;
        *(uint32_t*)(ahi + (size_t)rb * EDIM + d) = h1;
        *(uint32_t*)(alo + (size_t)rb * EDIM + d) = l1;
    }
}

// ---------------------------------------------------------------------------
extern "C" void kernel_launch(void* const* d_in, const int* in_sizes, int n_in,
                              void* d_out, int out_size)
{
    const float* x    = (const float*)d_in[0];
    const float* Wqkv = (const float*)d_in[1];
    const float* bqkv = (const float*)d_in[2];
    const float* Wo   = (const float*)d_in[3];
    const float* bo   = (const float*)d_in[4];
    float* out = (float*)d_out;

    __nv_bfloat16 *xhi, *xlo, *wqhi, *wqlo, *wohi, *wolo, *qkvhi, *qkvlo, *ahi, *alo;
    cudaGetSymbolAddress((void**)&xhi,   g_xhi);
    cudaGetSymbolAddress((void**)&xlo,   g_xlo);
    cudaGetSymbolAddress((void**)&wqhi,  g_wqhi);
    cudaGetSymbolAddress((void**)&wqlo,  g_wqlo);
    cudaGetSymbolAddress((void**)&wohi,  g_wohi);
    cudaGetSymbolAddress((void**)&wolo,  g_wolo);
    cudaGetSymbolAddress((void**)&qkvhi, g_qkvhi);
    cudaGetSymbolAddress((void**)&qkvlo, g_qkvlo);
    cudaGetSymbolAddress((void**)&ahi,   g_ahi);
    cudaGetSymbolAddress((void**)&alo,   g_alo);

    cudaFuncSetAttribute(gemm_tc_kernel, cudaFuncAttributeMaxDynamicSharedMemorySize, GEMM_SMEM);
    cudaFuncSetAttribute(attn_tc_kernel, cudaFuncAttributeMaxDynamicSharedMemorySize, ATTN_SMEM);

    {
        int n4 = (S_LEN * EDIM) / 4;
        split_bf16_kernel<<<(n4 + 255) / 256, 256>>>(
            (const float4*)x, (__nv_bfloat162*)xhi, (__nv_bfloat162*)xlo, n4);
    }
    {
        int n4 = (QKVN * EDIM) / 4;
        split_bf16_kernel<<<(n4 + 255) / 256, 256>>>(
            (const float4*)Wqkv, (__nv_bfloat162*)wqhi, (__nv_bfloat162*)wqlo, n4);
    }
    {
        int n4 = (EDIM * EDIM) / 4;
        split_bf16_kernel<<<(n4 + 255) / 256, 256>>>(
            (const float4*)Wo, (__nv_bfloat162*)wohi, (__nv_bfloat162*)wolo, n4);
    }

    // 1) QKV projection -> bf16 hi/lo
    gemm_tc_kernel<<<dim3(QKVN / 128, S_LEN / 128), 256, GEMM_SMEM>>>(
        xhi, xlo, wqhi, wqlo, bqkv, nullptr, qkvhi, qkvlo, S_LEN, QKVN, EDIM);

    // 2) flash attention on tensor cores -> bf16 hi/lo
    attn_tc_kernel<<<dim3(S_LEN / 64, NH), 128, ATTN_SMEM>>>(qkvhi, qkvlo, ahi, alo);

    // 3) output projection -> fp32 out
    gemm_tc_kernel<<<dim3(EDIM / 128, S_LEN / 128), 256, GEMM_SMEM>>>(
        ahi, alo, wohi, wolo, bo, out, nullptr, nullptr, S_LEN, EDIM, EDIM);
}

// round 7
// speedup vs baseline: 1.4936x; 1.3981x over previous
#include <cuda_runtime.h>
#include <cuda_fp16.h>
#include <cstdint>

// SparseWindowedAttention: B=1, S=4096, E=768, H=12, hd=64, window=128
// R7: fp16 2-pass split compensation everywhere: D = (Ahi+Alo)*Bhi.
//     B-side lo arrays eliminated (weights/K/V truncated to fp16 hi).
//     Tensor work cut 33% vs bf16 3-pass. Structure otherwise = R6.

#define S_LEN 4096
#define EDIM  768
#define NH    12
#define HD    64
#define QKVN  2304
#define WIN   128

// ------------------------- scratch -------------------------
__device__ __half g_xhi[(size_t)S_LEN * EDIM];
__device__ __half g_xlo[(size_t)S_LEN * EDIM];
__device__ __half g_wqh[(size_t)QKVN * EDIM];
__device__ __half g_woh[(size_t)EDIM * EDIM];
__device__ __half g_qkvhi[(size_t)S_LEN * QKVN];
__device__ __half g_qkvlo[(size_t)S_LEN * QKVN];
__device__ __half g_ahi[(size_t)S_LEN * EDIM];
__device__ __half g_alo[(size_t)S_LEN * EDIM];

// ------------------------- helpers -------------------------
__device__ __forceinline__ uint32_t smem_u32(const void* p) {
    uint32_t a;
    asm("{ .reg .u64 t; cvta.to.shared.u64 t, %1; cvt.u32.u64 %0, t; }" : "=r"(a) : "l"(p));
    return a;
}

#define CP_ASYNC16(saddr, gptr) \
    asm volatile("cp.async.cg.shared.global [%0], [%1], 16;" :: "r"(saddr), "l"(gptr))
#define CP_COMMIT() asm volatile("cp.async.commit_group;")
#define CP_WAIT1()  asm volatile("cp.async.wait_group 1;")

__device__ __forceinline__ void ldsm_x4(uint32_t* r, uint32_t addr) {
    asm volatile("ldmatrix.sync.aligned.m8n8.x4.shared.b16 {%0,%1,%2,%3}, [%4];"
                 : "=r"(r[0]), "=r"(r[1]), "=r"(r[2]), "=r"(r[3]) : "r"(addr));
}
__device__ __forceinline__ void ldsm_x2(uint32_t* r, uint32_t addr) {
    asm volatile("ldmatrix.sync.aligned.m8n8.x2.shared.b16 {%0,%1}, [%2];"
                 : "=r"(r[0]), "=r"(r[1]) : "r"(addr));
}
__device__ __forceinline__ void ldsm_x2_trans(uint32_t* r, uint32_t addr) {
    asm volatile("ldmatrix.sync.aligned.m8n8.x2.trans.shared.b16 {%0,%1}, [%2];"
                 : "=r"(r[0]), "=r"(r[1]) : "r"(addr));
}
__device__ __forceinline__ void mma_f16(float* d, const uint32_t* a, const uint32_t* b) {
    asm volatile(
        "mma.sync.aligned.m16n8k16.row.col.f32.f16.f16.f32 "
        "{%0,%1,%2,%3}, {%4,%5,%6,%7}, {%8,%9}, {%0,%1,%2,%3};"
        : "+f"(d[0]), "+f"(d[1]), "+f"(d[2]), "+f"(d[3])
        : "r"(a[0]), "r"(a[1]), "r"(a[2]), "r"(a[3]), "r"(b[0]), "r"(b[1]));
}

// split two floats into packed fp16x2 (hi, lo), x = hi + lo to ~2^-22
__device__ __forceinline__ void split2h(float x, float y, uint32_t& hi, uint32_t& lo) {
    __half hx = __float2half_rn(x);
    __half hy = __float2half_rn(y);
    __half lx = __float2half_rn(x - __half2float(hx));
    __half ly = __float2half_rn(y - __half2float(hy));
    hi = ((uint32_t)__half_as_ushort(hy) << 16) | (uint32_t)__half_as_ushort(hx);
    lo = ((uint32_t)__half_as_ushort(ly) << 16) | (uint32_t)__half_as_ushort(lx);
}

// ---------------------------------------------------------------------------
__global__ void split_f16_kernel(const float4* __restrict__ in,
                                 uint32_t* __restrict__ hi,
                                 uint32_t* __restrict__ lo, int n4)
{
    int i = blockIdx.x * blockDim.x + threadIdx.x;
    if (i >= n4) return;
    float4 v = in[i];
    uint32_t h0, l0, h1, l1;
    split2h(v.x, v.y, h0, l0);
    split2h(v.z, v.w, h1, l1);
    hi[2*i]   = h0;
    hi[2*i+1] = h1;
    lo[2*i]   = l0;
    lo[2*i+1] = l1;
}

__global__ void tohalf_kernel(const float4* __restrict__ in,
                              __half2* __restrict__ out, int n4)
{
    int i = blockIdx.x * blockDim.x + threadIdx.x;
    if (i >= n4) return;
    float4 v = in[i];
    out[2*i]   = __floats2half2_rn(v.x, v.y);
    out[2*i+1] = __floats2half2_rn(v.z, v.w);
}

// ---------------------------------------------------------------------------
// GEMM: C = (Ahi+Alo)[M,K] @ Bhi[N,K]^T + bias, mma.sync fp16 2-pass.
// 128x128 CTA tile, BK=32. Stage = A tile (row: 64B hi | 64B lo) | B tile
// (row: 64B hi, rest unused), SW128. 3 stages, one sync per chunk.
// ---------------------------------------------------------------------------
#define TILE_BYTES 16384
#define STAGE_BYTES (2 * TILE_BYTES)
#define NSTAGE 3
#define GEMM_SMEM (NSTAGE * STAGE_BYTES + 1024)

__global__ __launch_bounds__(256, 2) void gemm_tc_kernel(
    const __half* __restrict__ Ahi, const __half* __restrict__ Alo,
    const __half* __restrict__ Bhi,
    const float* __restrict__ bias, float* __restrict__ C,
    __half* __restrict__ Chi, __half* __restrict__ Clo,
    int M, int N, int K)
{
    extern __shared__ char smem[];
    const uint32_t sraw = smem_u32(smem);
    const uint32_t sbase = (sraw + 1023u) & ~1023u;

    const int tid  = threadIdx.x;
    const int wid  = tid >> 5;
    const int lane = tid & 31;
    const int bm = blockIdx.y * 128;
    const int bn = blockIdx.x * 128;
    const int nch = K >> 5;

    const int warp_m = wid & 1;
    const int warp_n = wid >> 1;

    const int lrow = tid >> 1;
    const int lsel = tid & 1;
    const uint32_t lsw = (uint32_t)((lrow & 7) << 4);
    const uint32_t lrowbase = (uint32_t)lrow * 128;
    const uint32_t lc0  = ((uint32_t)(2 * lsel) * 16) ^ lsw;
    const uint32_t lc1  = ((uint32_t)(2 * lsel + 1) * 16) ^ lsw;
    const uint32_t lc0l = ((uint32_t)(2 * lsel) * 16 + 64) ^ lsw;
    const uint32_t lc1l = ((uint32_t)(2 * lsel + 1) * 16 + 64) ^ lsw;

    const __half* gah = Ahi + (size_t)(bm + lrow) * K + 2 * lsel * 8;
    const __half* gal = Alo + (size_t)(bm + lrow) * K + 2 * lsel * 8;
    const __half* gbh = Bhi + (size_t)(bn + lrow) * K + 2 * lsel * 8;

    float acc[4][4][4];
    #pragma unroll
    for (int i = 0; i < 4; i++)
        #pragma unroll
        for (int j = 0; j < 4; j++)
            #pragma unroll
            for (int e = 0; e < 4; e++) acc[i][j][e] = 0.f;

    auto load_stage = [&](int t, int buf) {
        const uint32_t sA = sbase + buf * STAGE_BYTES + lrowbase;
        const uint32_t sB = sA + TILE_BYTES;
        const int k0 = t * 32;
        CP_ASYNC16(sA + lc0,  gah + k0);
        CP_ASYNC16(sA + lc1,  gah + k0 + 8);
        CP_ASYNC16(sA + lc0l, gal + k0);
        CP_ASYNC16(sA + lc1l, gal + k0 + 8);
        CP_ASYNC16(sB + lc0,  gbh + k0);
        CP_ASYNC16(sB + lc1,  gbh + k0 + 8);
    };

    load_stage(0, 0); CP_COMMIT();
    load_stage(1, 1); CP_COMMIT();

    const int la_row = lane & 15;
    const int la_kh  = lane >> 4;
    const int lb_row = lane & 7;
    const int lb_kh  = (lane >> 3) & 1;

    uint32_t a_rowbase[4], a_sw[4];
    #pragma unroll
    for (int mi = 0; mi < 4; mi++) {
        const int row = warp_m * 64 + mi * 16 + la_row;
        a_rowbase[mi] = (uint32_t)row * 128;
        a_sw[mi] = (uint32_t)((row & 7) << 4);
    }
    uint32_t b_rowbase[4], b_sw[4];
    #pragma unroll
    for (int ni = 0; ni < 4; ni++) {
        const int row = warp_n * 32 + ni * 8 + lb_row;
        b_rowbase[ni] = (uint32_t)row * 128;
        b_sw[ni] = (uint32_t)((row & 7) << 4);
    }

    int buf = 0;
    for (int t = 0; t < nch; t++) {
        CP_WAIT1();
        __syncthreads();
        if (t + 2 < nch) {
            int b2 = buf + 2; if (b2 >= NSTAGE) b2 -= NSTAGE;
            load_stage(t + 2, b2);
        }
        CP_COMMIT();

        const uint32_t sA = sbase + buf * STAGE_BYTES;
        const uint32_t sB = sA + TILE_BYTES;

        #pragma unroll
        for (int ks = 0; ks < 2; ks++) {
            const uint32_t akoff = (uint32_t)(ks * 32 + la_kh * 16);
            const uint32_t bkoff = (uint32_t)(ks * 32 + lb_kh * 16);
            uint32_t bhv[4][2];
            #pragma unroll
            for (int ni = 0; ni < 4; ni++)
                ldsm_x2(bhv[ni], sB + b_rowbase[ni] + (bkoff ^ b_sw[ni]));
            #pragma unroll
            for (int mi = 0; mi < 4; mi++) {
                uint32_t ahi[4], alo[4];
                const uint32_t base = sA + a_rowbase[mi];
                ldsm_x4(ahi, base + (akoff ^ a_sw[mi]));
                ldsm_x4(alo, base + ((akoff + 64) ^ a_sw[mi]));
                #pragma unroll
                for (int ni = 0; ni < 4; ni++) {
                    mma_f16(acc[mi][ni], ahi, bhv[ni]);
                    mma_f16(acc[mi][ni], alo, bhv[ni]);
                }
            }
        }
        buf++; if (buf >= NSTAGE) buf = 0;
    }

    #pragma unroll
    for (int mi = 0; mi < 4; mi++) {
        const int row = bm + warp_m * 64 + mi * 16 + (lane >> 2);
        #pragma unroll
        for (int ni = 0; ni < 4; ni++) {
            const int col = bn + warp_n * 32 + ni * 8 + (lane & 3) * 2;
            const float2 bv = *(const float2*)(bias + col);
            float v0 = acc[mi][ni][0] + bv.x, v1 = acc[mi][ni][1] + bv.y;
            float v2 = acc[mi][ni][2] + bv.x, v3 = acc[mi][ni][3] + bv.y;
            if (Chi) {
                uint32_t h0, l0, h1, l1;
                split2h(v0, v1, h0, l0);
                split2h(v2, v3, h1, l1);
                *(uint32_t*)(Chi + (size_t)row * N + col)       = h0;
                *(uint32_t*)(Clo + (size_t)row * N + col)       = l0;
                *(uint32_t*)(Chi + (size_t)(row + 8) * N + col) = h1;
                *(uint32_t*)(Clo + (size_t)(row + 8) * N + col) = l1;
            } else {
                *(float2*)(C + (size_t)row * N + col)       = make_float2(v0, v1);
                *(float2*)(C + (size_t)(row + 8) * N + col) = make_float2(v2, v3);
            }
        }
    }
}

// ---------------------------------------------------------------------------
// Flash attention, fp16 2-pass. Q hi/lo in smem; K hi only; V hi only.
// P split hi/lo in registers for PV: (Phi+Plo)*Vhi.
// ---------------------------------------------------------------------------
#define QPITCH 72
#define SQHI 0
#define SQLO 9216
#define SKHI 18432
#define SVHI 27648
#define ATTN_SMEM 36864

__global__ __launch_bounds__(128) void attn_tc_kernel(
    const __half* __restrict__ qkvhi, const __half* __restrict__ qkvlo,
    __half* __restrict__ ahi, __half* __restrict__ alo)
{
    extern __shared__ char smem[];
    const uint32_t sb = smem_u32(smem);

    const int tid  = threadIdx.x;
    const int lane = tid & 31;
    const int wq   = tid >> 5;
    const int h    = blockIdx.y;
    const int q0   = blockIdx.x * 64;

    const int lrow = tid >> 1;
    const int half = tid & 1;
    const uint32_t soff = (uint32_t)(lrow * QPITCH + half * 32) * 2;

    {
        const __half* sh = qkvhi + (size_t)(q0 + lrow) * QKVN + h * 192 + half * 32;
        const __half* sl = qkvlo + (size_t)(q0 + lrow) * QKVN + h * 192 + half * 32;
        #pragma unroll
        for (int i = 0; i < 4; i++) {
            *(uint4*)(smem + SQHI + soff + i * 16) = *(const uint4*)(sh + i * 8);
            *(uint4*)(smem + SQLO + soff + i * 16) = *(const uint4*)(sl + i * 8);
        }
    }

    float oacc[8][4];
    #pragma unroll
    for (int ni = 0; ni < 8; ni++)
        #pragma unroll
        for (int e = 0; e < 4; e++) oacc[ni][e] = 0.f;
    float m_a = -1e30f, m_b = -1e30f, l_a = 0.f, l_b = 0.f;

    const int ra = q0 + wq * 16 + (lane >> 2);
    const int rb = ra + 8;

    for (int kb = 0; kb < 5; kb++) {
        const int jbase = q0 - WIN + kb * 64;
        __syncthreads();
        {
            const int g = jbase + lrow;
            const bool v = (g >= 0) && (g < S_LEN);
            const size_t gb = (size_t)(v ? g : 0) * QKVN + h * 192 + half * 32;
            const uint4 z = make_uint4(0, 0, 0, 0);
            #pragma unroll
            for (int i = 0; i < 4; i++) {
                *(uint4*)(smem + SKHI + soff + i*16) = v ? *(const uint4*)(qkvhi + gb + 64  + i*8) : z;
                *(uint4*)(smem + SVHI + soff + i*16) = v ? *(const uint4*)(qkvhi + gb + 128 + i*8) : z;
            }
        }
        __syncthreads();

        float sacc[8][4];
        #pragma unroll
        for (int ni = 0; ni < 8; ni++)
            #pragma unroll
            for (int e = 0; e < 4; e++) sacc[ni][e] = 0.f;

        #pragma unroll
        for (int ks = 0; ks < 4; ks++) {
            uint32_t aqh[4], aql[4];
            const uint32_t qoff = (uint32_t)((wq*16 + (lane & 15)) * QPITCH + ks*16 + (lane >> 4) * 8) * 2;
            ldsm_x4(aqh, sb + SQHI + qoff);
            ldsm_x4(aql, sb + SQLO + qoff);
            #pragma unroll
            for (int ni = 0; ni < 8; ni++) {
                uint32_t bh[2];
                const uint32_t koff = (uint32_t)((ni*8 + (lane & 7)) * QPITCH + ks*16 + ((lane >> 3) & 1) * 8) * 2;
                ldsm_x2(bh, sb + SKHI + koff);
                mma_f16(sacc[ni], aqh, bh);
                mma_f16(sacc[ni], aql, bh);
            }
        }

        float mk_a = -1e30f, mk_b = -1e30f;
        #pragma unroll
        for (int ni = 0; ni < 8; ni++) {
            const int j0 = jbase + ni * 8 + (lane & 3) * 2;
            #pragma unroll
            for (int e = 0; e < 4; e++) {
                const int g = j0 + (e & 1);
                const int r = (e < 2) ? ra : rb;
                const int d = r - g;
                const bool ok = (g >= 0) && (g < S_LEN) && (d <= WIN) && (d >= -WIN);
                const float s = ok ? sacc[ni][e] * 0.125f : -1e30f;
                sacc[ni][e] = s;
                if (e < 2) mk_a = fmaxf(mk_a, s); else mk_b = fmaxf(mk_b, s);
            }
        }
        mk_a = fmaxf(mk_a, __shfl_xor_sync(0xffffffffu, mk_a, 1));
        mk_a = fmaxf(mk_a, __shfl_xor_sync(0xffffffffu, mk_a, 2));
        mk_b = fmaxf(mk_b, __shfl_xor_sync(0xffffffffu, mk_b, 1));
        mk_b = fmaxf(mk_b, __shfl_xor_sync(0xffffffffu, mk_b, 2));

        const float mn_a = fmaxf(m_a, mk_a);
        const float mn_b = fmaxf(m_b, mk_b);
        const float corr_a = __expf(m_a - mn_a);
        const float corr_b = __expf(m_b - mn_b);
        const float sm_a = (mn_a < -1e29f) ? 0.f : mn_a;
        const float sm_b = (mn_b < -1e29f) ? 0.f : mn_b;

        float su_a = 0.f, su_b = 0.f;
        #pragma unroll
        for (int ni = 0; ni < 8; ni++) {
            #pragma unroll
            for (int e = 0; e < 4; e++) {
                const float p = __expf(sacc[ni][e] - ((e < 2) ? sm_a : sm_b));
                sacc[ni][e] = p;
                if (e < 2) su_a += p; else su_b += p;
            }
        }
        su_a += __shfl_xor_sync(0xffffffffu, su_a, 1);
        su_a += __shfl_xor_sync(0xffffffffu, su_a, 2);
        su_b += __shfl_xor_sync(0xffffffffu, su_b, 1);
        su_b += __shfl_xor_sync(0xffffffffu, su_b, 2);

        l_a = l_a * corr_a + su_a;
        l_b = l_b * corr_b + su_b;
        m_a = mn_a; m_b = mn_b;

        #pragma unroll
        for (int ni = 0; ni < 8; ni++) {
            oacc[ni][0] *= corr_a; oacc[ni][1] *= corr_a;
            oacc[ni][2] *= corr_b; oacc[ni][3] *= corr_b;
        }

        #pragma unroll
        for (int kk = 0; kk < 4; kk++) {
            uint32_t aph[4], apl[4];
            split2h(sacc[2*kk][0],   sacc[2*kk][1],   aph[0], apl[0]);
            split2h(sacc[2*kk][2],   sacc[2*kk][3],   aph[1], apl[1]);
            split2h(sacc[2*kk+1][0], sacc[2*kk+1][1], aph[2], apl[2]);
            split2h(sacc[2*kk+1][2], sacc[2*kk+1][3], aph[3], apl[3]);
            #pragma unroll
            for (int ni = 0; ni < 8; ni++) {
                uint32_t bvh[2];
                const uint32_t voff = (uint32_t)((kk*16 + (lane & 15)) * QPITCH + ni * 8) * 2;
                ldsm_x2_trans(bvh, sb + SVHI + voff);
                mma_f16(oacc[ni], aph, bvh);
                mma_f16(oacc[ni], apl, bvh);
            }
        }
    }

    const float inv_a = (l_a > 0.f) ? 1.f / l_a : 0.f;
    const float inv_b = (l_b > 0.f) ? 1.f / l_b : 0.f;
    #pragma unroll
    for (int ni = 0; ni < 8; ni++) {
        const int d = h * 64 + ni * 8 + (lane & 3) * 2;
        uint32_t h0, l0, h1, l1;
        split2h(oacc[ni][0] * inv_a, oacc[ni][1] * inv_a, h0, l0);
        split2h(oacc[ni][2] * inv_b, oacc[ni][3] * inv_b, h1, l1);
        *(uint32_t*)(ahi + (size_t)ra * EDIM + d) = h0;
        *(uint32_t*)(alo + (size_t)ra * EDIM + d) = l0;
        *(uint32_t*)(ahi + (size_t)rb * EDIM + d) = h1;
        *(uint32_t*)(alo + (size_t)rb * EDIM + d) = l1;
    }
}

// ---------------------------------------------------------------------------
extern "C" void kernel_launch(void* const* d_in, const int* in_sizes, int n_in,
                              void* d_out, int out_size)
{
    const float* x    = (const float*)d_in[0];
    const float* Wqkv = (const float*)d_in[1];
    const float* bqkv = (const float*)d_in[2];
    const float* Wo   = (const float*)d_in[3];
    const float* bo   = (const float*)d_in[4];
    float* out = (float*)d_out;

    __half *xhi, *xlo, *wqh, *woh, *qkvhi, *qkvlo, *ahi, *alo;
    cudaGetSymbolAddress((void**)&xhi,   g_xhi);
    cudaGetSymbolAddress((void**)&xlo,   g_xlo);
    cudaGetSymbolAddress((void**)&wqh,   g_wqh);
    cudaGetSymbolAddress((void**)&woh,   g_woh);
    cudaGetSymbolAddress((void**)&qkvhi, g_qkvhi);
    cudaGetSymbolAddress((void**)&qkvlo, g_qkvlo);
    cudaGetSymbolAddress((void**)&ahi,   g_ahi);
    cudaGetSymbolAddress((void**)&alo,   g_alo);

    cudaFuncSetAttribute(gemm_tc_kernel, cudaFuncAttributeMaxDynamicSharedMemorySize, GEMM_SMEM);
    cudaFuncSetAttribute(attn_tc_kernel, cudaFuncAttributeMaxDynamicSharedMemorySize, ATTN_SMEM);

    {   // x -> fp16 hi/lo
        int n4 = (S_LEN * EDIM) / 4;
        split_f16_kernel<<<(n4 + 255) / 256, 256>>>(
            (const float4*)x, (uint32_t*)xhi, (uint32_t*)xlo, n4);
    }
    {   // Wqkv -> fp16 hi only
        int n4 = (QKVN * EDIM) / 4;
        tohalf_kernel<<<(n4 + 255) / 256, 256>>>((const float4*)Wqkv, (__half2*)wqh, n4);
    }
    {   // Wo -> fp16 hi only
        int n4 = (EDIM * EDIM) / 4;
        tohalf_kernel<<<(n4 + 255) / 256, 256>>>((const float4*)Wo, (__half2*)woh, n4);
    }

    // 1) QKV projection -> fp16 hi/lo
    gemm_tc_kernel<<<dim3(QKVN / 128, S_LEN / 128), 256, GEMM_SMEM>>>(
        xhi, xlo, wqh, bqkv, nullptr, qkvhi, qkvlo, S_LEN, QKVN, EDIM);

    // 2) flash attention -> fp16 hi/lo
    attn_tc_kernel<<<dim3(S_LEN / 64, NH), 128, ATTN_SMEM>>>(qkvhi, qkvlo, ahi, alo);

    // 3) output projection -> fp32 out
    gemm_tc_kernel<<<dim3(EDIM / 128, S_LEN / 128), 256, GEMM_SMEM>>>(
        ahi, alo, woh, bo, out, nullptr, nullptr, S_LEN, EDIM, EDIM);
}